// round 16
// baseline (speedup 1.0000x reference)
#include <cuda_runtime.h>
#include <stdint.h>

// EdgeFeaturizer FINAL: one row/block, 4x8KB fire-and-forget cp.async.bulk
// staging (TMA path, zero LDG pressure), occ 6, exact threshold-compaction
// with fallback, parallel rank selection, stage-free parallel expf tail.
//
// At the measured B300 LTS ceiling: 288.9 MB total L2 traffic / ~6.3 TB/s
// ≈ 45.8 us kernel time — which this kernel achieves (ncu 45.2-45.3 us).

#define N_ATOMS   8192
#define KNBR      12
#define NBINS     50
#define CAP       192
#define THREADS   256
#define T0        0.0035f
#define CHUNKS    4
#define CHUNK_F   2048          // floats per chunk (8 KB)
#define CHUNK_V   512           // float4 per chunk

__device__ __forceinline__ unsigned smem_u32(const void* p) {
    return (unsigned)__cvta_generic_to_shared(p);
}

__device__ __forceinline__ void mbar_wait0(unsigned mb) {
    unsigned done;
    asm volatile(
        "{\n\t.reg .pred p;\n\t"
        "mbarrier.try_wait.parity.acquire.cta.shared::cta.b64 p, [%1], 0;\n\t"
        "selp.b32 %0, 1, 0, p;\n\t}"
        : "=r"(done) : "r"(mb) : "memory");
    if (!done) {
        asm volatile(
            "{\n\t.reg .pred P1;\n\t"
            "WL_%=:\n\t"
            "mbarrier.try_wait.parity.acquire.cta.shared::cta.b64 P1, [%0], 0, 0x989680;\n\t"
            "@P1 bra.uni WD_%=;\n\t"
            "bra.uni WL_%=;\n\t"
            "WD_%=:\n\t}"
            :: "r"(mb) : "memory");
    }
}

__global__ __launch_bounds__(THREADS, 6)
void edge_featurizer_kernel(const float* __restrict__ dm, float* __restrict__ out)
{
    __shared__ __align__(128) float s_row[N_ATOMS];     // 32 KB row stage
    __shared__ unsigned long long cand[CAP];
    __shared__ int   s_cnt;
    __shared__ float s_d[KNBR];
    __shared__ int   s_i[KNBR];
    __shared__ __align__(8) unsigned long long s_mbar[CHUNKS];

    const int tid = threadIdx.x;
    const int row = blockIdx.x;

    if (tid == 0) {
        s_cnt = 0;
        #pragma unroll
        for (int c = 0; c < CHUNKS; c++)
            asm volatile("mbarrier.init.shared.b64 [%0], 1;"
                         :: "r"(smem_u32(&s_mbar[c])) : "memory");
    }
    __syncthreads();

    // ---- issue all 4 bulk copies up front (fire-and-forget TMA path) ----
    if (tid == 0) {
        const char* src = (const char*)(dm + (size_t)row * N_ATOMS);
        #pragma unroll
        for (int c = 0; c < CHUNKS; c++) {
            unsigned mb  = smem_u32(&s_mbar[c]);
            unsigned dst = smem_u32(&s_row[c * CHUNK_F]);
            asm volatile("mbarrier.arrive.expect_tx.shared.b64 _, [%0], %1;"
                         :: "r"(mb), "r"(CHUNK_F * 4) : "memory");
            asm volatile(
                "cp.async.bulk.shared::cta.global.mbarrier::complete_tx::bytes "
                "[%0], [%1], %2, [%3];"
                :: "r"(dst), "l"(src + (size_t)c * CHUNK_F * 4),
                   "r"(CHUNK_F * 4), "r"(mb) : "memory");
        }
    }

    const float4* s4 = reinterpret_cast<const float4*>(s_row);

    // ---- Phase 1: chunk-pipelined scan from SMEM ----
    #pragma unroll
    for (int c = 0; c < CHUNKS; c++) {
        mbar_wait0(smem_u32(&s_mbar[c]));
        const int i0 = c * CHUNK_V + tid;
        const int i1 = i0 + THREADS;
        float4 v0 = s4[i0];
        float4 v1 = s4[i1];
        float m0 = fminf(fminf(v0.x, v0.y), fminf(v0.z, v0.w));
        float m1 = fminf(fminf(v1.x, v1.y), fminf(v1.z, v1.w));
        if (fminf(m0, m1) < T0) {                     // rare per-thread body
            #pragma unroll
            for (int j = 0; j < 2; j++) {
                float4 v = (j == 0) ? v0 : v1;
                int    i = (j == 0) ? i0 : i1;
                int h = (v.x < T0) + (v.y < T0) + (v.z < T0) + (v.w < T0);
                if (h) {
                    int p = atomicAdd(&s_cnt, h);
                    unsigned base = 4u * (unsigned)i;
                    if (v.x < T0 && p < CAP)
                        cand[p++] = (((unsigned long long)__float_as_uint(v.x)) << 32) | (base + 0u);
                    if (v.y < T0 && p < CAP)
                        cand[p++] = (((unsigned long long)__float_as_uint(v.y)) << 32) | (base + 1u);
                    if (v.z < T0 && p < CAP)
                        cand[p++] = (((unsigned long long)__float_as_uint(v.z)) << 32) | (base + 2u);
                    if (v.w < T0 && p < CAP)
                        cand[p++] = (((unsigned long long)__float_as_uint(v.w)) << 32) | (base + 3u);
                }
            }
        }
    }
    __syncthreads();

    // ---- exact fallback: rescan from SMEM with adjusted t (rare) ----
    int c = s_cnt;
    float t = T0;
    while (c < KNBR || c > CAP) {
        t = (c < KNBR) ? t * 8.0f : t * 0.25f;
        __syncthreads();
        if (tid == 0) s_cnt = 0;
        __syncthreads();
        #pragma unroll
        for (int ii = 0; ii < N_ATOMS / 4 / THREADS; ii++) {
            int i = tid + ii * THREADS;
            float4 v = s4[i];
            if (fminf(fminf(v.x, v.y), fminf(v.z, v.w)) < t) {
                int h = (v.x < t) + (v.y < t) + (v.z < t) + (v.w < t);
                int p = atomicAdd(&s_cnt, h);
                unsigned base = 4u * (unsigned)i;
                if (v.x < t && p < CAP)
                    cand[p++] = (((unsigned long long)__float_as_uint(v.x)) << 32) | (base + 0u);
                if (v.y < t && p < CAP)
                    cand[p++] = (((unsigned long long)__float_as_uint(v.y)) << 32) | (base + 1u);
                if (v.z < t && p < CAP)
                    cand[p++] = (((unsigned long long)__float_as_uint(v.z)) << 32) | (base + 2u);
                if (v.w < t && p < CAP)
                    cand[p++] = (((unsigned long long)__float_as_uint(v.w)) << 32) | (base + 3u);
            }
        }
        __syncthreads();
        c = s_cnt;
        __syncthreads();
    }

    // ---- Phase 2: parallel rank selection (keys unique -> ranks distinct) ----
    if (tid < c) {
        unsigned long long mine = cand[tid];
        int rank = 0;
        int j = 0;
        for (; j + 4 <= c; j += 4) {
            rank += (cand[j + 0] < mine);
            rank += (cand[j + 1] < mine);
            rank += (cand[j + 2] < mine);
            rank += (cand[j + 3] < mine);
        }
        for (; j < c; j++) rank += (cand[j] < mine);
        if (rank < KNBR) {
            s_d[rank] = __uint_as_float((unsigned)(mine >> 32));
            s_i[rank] = (int)(mine & 0xffffffffu);
        }
    }
    __syncthreads();

    // ---- Phase 3: fully parallel output (stage-free) ----
    if (tid < KNBR) {                          // one 64-bit store per edge
        float2 e = make_float2((float)row, (float)s_i[tid]);
        reinterpret_cast<float2*>(out)[(size_t)row * KNBR + tid] = e;
    }
    float* __restrict__ outF = out + (size_t)N_ATOMS * KNBR * 2
                                   + (size_t)row * (KNBR * NBINS);
    {
        // strength-reduced (e,j) tracking: tid stride 256 over 600 outputs
        int e = tid / NBINS;
        int j = tid - e * NBINS;
        #pragma unroll
        for (int i = tid; i < KNBR * NBINS; i += THREADS) {
            float z = (s_d[e] - (float)j * (1.0f / 49.0f)) * 5.0f;  // /WIDTH=0.2
            outF[i] = __expf(-0.5f * z * z);
            j += THREADS - 5 * NBINS;          // 256 = 5*50 + 6
            e += 5;
            if (j >= NBINS) { j -= NBINS; e += 1; }
            else if (j < 0) { j += NBINS; e -= 1; }
        }
    }
}

extern "C" void kernel_launch(void* const* d_in, const int* in_sizes, int n_in,
                              void* d_out, int out_size)
{
    (void)in_sizes; (void)n_in; (void)out_size;
    const float* dm = (const float*)d_in[0];
    float* out = (float*)d_out;
    edge_featurizer_kernel<<<N_ATOMS, THREADS>>>(dm, out);
}